// round 10
// baseline (speedup 1.0000x reference)
#include <cuda_runtime.h>
#include <math.h>
#include <stddef.h>

// Problem constants
#define BB 2
#define SS 2048
#define DM 1024
#define NH 16
#define DK 64
#define BHX (BB * NH)     // 32
#define NTILES (SS / 128) // 16 column tiles per row

// ---------------------------------------------------------------------------
// Scratch (device globals; no allocation allowed)
// ---------------------------------------------------------------------------
__device__ float g_Q [(size_t)BB * SS * DM];
__device__ float g_Kp[(size_t)BB * SS * DK];
__device__ float g_Vp[(size_t)BB * SS * DK];
__device__ float g_AO[(size_t)BB * SS * DM];
__device__ float g_attn_scratch[(size_t)BB * NH * SS * SS];

// Softmax split stats
__device__ float g_pm[BHX][NTILES][SS];   // per column-tile partial max
__device__ float g_ps[BHX][NTILES][SS];   // per column-tile partial sumexp
__device__ float g_rowM [BHX][SS];        // final row max
__device__ float g_rowIS[BHX][SS];        // final 1/rowsum

// ---------------------------------------------------------------------------
// TF32 helpers (fragment layouts validated in R7)
// ---------------------------------------------------------------------------
__device__ __forceinline__ unsigned f2tf(float x) {
    unsigned r;
    asm("cvt.rna.tf32.f32 %0, %1;" : "=r"(r) : "f"(x));
    return r;
}

__device__ __forceinline__ void mma_tf32(float c[4], const unsigned a[4], const unsigned b[2]) {
    asm volatile(
        "mma.sync.aligned.m16n8k8.row.col.f32.tf32.tf32.f32 "
        "{%0,%1,%2,%3}, {%4,%5,%6,%7}, {%8,%9}, {%0,%1,%2,%3};"
        : "+f"(c[0]), "+f"(c[1]), "+f"(c[2]), "+f"(c[3])
        : "r"(a[0]), "r"(a[1]), "r"(a[2]), "r"(a[3]), "r"(b[0]), "r"(b[1]));
}

__device__ __forceinline__ void split_tf32(float x, unsigned& hi, unsigned& lo) {
    hi = f2tf(x);
    lo = f2tf(x - __uint_as_float(hi));
}

// ---------------------------------------------------------------------------
// SIMT fp32 GEMM with bias (small K/V projections, N=64)
// ---------------------------------------------------------------------------
__global__ void gemm_bias_kernel(const float* __restrict__ A,
                                 const float* __restrict__ W,
                                 const float* __restrict__ bias,
                                 float* __restrict__ C,
                                 int M, int K, int N) {
    __shared__ float As[16][68];
    __shared__ float Ws[16][64];

    const int tid = threadIdx.x;
    const int tx = tid & 15;
    const int ty = tid >> 4;
    const int bm = blockIdx.x * 64;
    const int bn = blockIdx.y * 64;

    float acc[4][4] = {};

    for (int k0 = 0; k0 < K; k0 += 16) {
        #pragma unroll
        for (int i = tid; i < 64 * 16; i += 256) {
            int m = i >> 4, k = i & 15;
            As[k][m] = A[(size_t)(bm + m) * K + k0 + k];
        }
        #pragma unroll
        for (int i = tid; i < 16 * 64; i += 256) {
            int k = i >> 6, n = i & 63;
            Ws[k][n] = W[(size_t)(k0 + k) * N + bn + n];
        }
        __syncthreads();

        #pragma unroll
        for (int k = 0; k < 16; k++) {
            float4 avv = *reinterpret_cast<const float4*>(&As[k][ty * 4]);
            float a[4] = {avv.x, avv.y, avv.z, avv.w};
            float4 bv = *reinterpret_cast<const float4*>(&Ws[k][tx * 4]);
            float b[4] = {bv.x, bv.y, bv.z, bv.w};
            #pragma unroll
            for (int i = 0; i < 4; i++)
                #pragma unroll
                for (int j = 0; j < 4; j++)
                    acc[i][j] = fmaf(a[i], b[j], acc[i][j]);
        }
        __syncthreads();
    }

    #pragma unroll
    for (int i = 0; i < 4; i++) {
        int m = bm + ty * 4 + i;
        #pragma unroll
        for (int j = 0; j < 4; j++) {
            int n = bn + tx * 4 + j;
            C[(size_t)m * N + n] = acc[i][j] + bias[n];
        }
    }
}

// ---------------------------------------------------------------------------
// 3xTF32 tensor-core GEMM with bias (big projections)
// ---------------------------------------------------------------------------
__global__ void gemm_bias_tf32x3_kernel(const float* __restrict__ A,
                                        const float* __restrict__ W,
                                        const float* __restrict__ bias,
                                        float* __restrict__ C,
                                        int M, int K, int N) {
    __shared__ unsigned Ah[128][20];
    __shared__ unsigned Al[128][20];
    __shared__ unsigned Wh[128][20];
    __shared__ unsigned Wl[128][20];

    const int tid = threadIdx.x;
    const int warp = tid >> 5;
    const int lane = tid & 31;
    const int wm = (warp >> 2) * 64;
    const int wn = (warp & 3) * 32;
    const int lr = lane >> 2;
    const int lc = lane & 3;
    const int bm = blockIdx.x * 128;
    const int bn = blockIdx.y * 128;

    float c[4][4][4] = {};

    for (int k0 = 0; k0 < K; k0 += 16) {
        {
            const int r = tid >> 1;
            const int cb = (tid & 1) * 8;
            const float* src = &A[(size_t)(bm + r) * K + k0 + cb];
            #pragma unroll
            for (int i = 0; i < 2; i++) {
                float4 v = *reinterpret_cast<const float4*>(src + i * 4);
                unsigned hi, lo;
                split_tf32(v.x, hi, lo); Ah[r][cb + i*4 + 0] = hi; Al[r][cb + i*4 + 0] = lo;
                split_tf32(v.y, hi, lo); Ah[r][cb + i*4 + 1] = hi; Al[r][cb + i*4 + 1] = lo;
                split_tf32(v.z, hi, lo); Ah[r][cb + i*4 + 2] = hi; Al[r][cb + i*4 + 2] = lo;
                split_tf32(v.w, hi, lo); Ah[r][cb + i*4 + 3] = hi; Al[r][cb + i*4 + 3] = lo;
            }
        }
        {
            const int kk = tid >> 4;
            const int nb = (tid & 15) * 8;
            const float* src = &W[(size_t)(k0 + kk) * N + bn + nb];
            #pragma unroll
            for (int i = 0; i < 2; i++) {
                float4 v = *reinterpret_cast<const float4*>(src + i * 4);
                unsigned hi, lo;
                split_tf32(v.x, hi, lo); Wh[nb + i*4 + 0][kk] = hi; Wl[nb + i*4 + 0][kk] = lo;
                split_tf32(v.y, hi, lo); Wh[nb + i*4 + 1][kk] = hi; Wl[nb + i*4 + 1][kk] = lo;
                split_tf32(v.z, hi, lo); Wh[nb + i*4 + 2][kk] = hi; Wl[nb + i*4 + 2][kk] = lo;
                split_tf32(v.w, hi, lo); Wh[nb + i*4 + 3][kk] = hi; Wl[nb + i*4 + 3][kk] = lo;
            }
        }
        __syncthreads();

        #pragma unroll
        for (int ks = 0; ks < 2; ks++) {
            const int kb = ks * 8;
            unsigned ah[4][4], al[4][4], bh[4][2], bl[4][2];
            #pragma unroll
            for (int mt = 0; mt < 4; mt++) {
                int r0 = wm + mt * 16 + lr;
                ah[mt][0] = Ah[r0    ][kb + lc];
                ah[mt][1] = Ah[r0 + 8][kb + lc];
                ah[mt][2] = Ah[r0    ][kb + 4 + lc];
                ah[mt][3] = Ah[r0 + 8][kb + 4 + lc];
                al[mt][0] = Al[r0    ][kb + lc];
                al[mt][1] = Al[r0 + 8][kb + lc];
                al[mt][2] = Al[r0    ][kb + 4 + lc];
                al[mt][3] = Al[r0 + 8][kb + 4 + lc];
            }
            #pragma unroll
            for (int nt = 0; nt < 4; nt++) {
                int n0 = wn + nt * 8 + lr;
                bh[nt][0] = Wh[n0][kb + lc];
                bh[nt][1] = Wh[n0][kb + 4 + lc];
                bl[nt][0] = Wl[n0][kb + lc];
                bl[nt][1] = Wl[n0][kb + 4 + lc];
            }
            #pragma unroll
            for (int mt = 0; mt < 4; mt++)
                #pragma unroll
                for (int nt = 0; nt < 4; nt++) {
                    mma_tf32(c[mt][nt], al[mt], bh[nt]);
                    mma_tf32(c[mt][nt], ah[mt], bl[nt]);
                    mma_tf32(c[mt][nt], ah[mt], bh[nt]);
                }
        }
        __syncthreads();
    }

    #pragma unroll
    for (int mt = 0; mt < 4; mt++) {
        #pragma unroll
        for (int half = 0; half < 2; half++) {
            int m = bm + wm + mt * 16 + lr + half * 8;
            #pragma unroll
            for (int nt = 0; nt < 4; nt++) {
                int n = bn + wn + nt * 8 + lc * 2;
                float2 bv = *reinterpret_cast<const float2*>(&bias[n]);
                float2 v;
                v.x = c[mt][nt][half * 2 + 0] + bv.x;
                v.y = c[mt][nt][half * 2 + 1] + bv.y;
                *reinterpret_cast<float2*>(&C[(size_t)m * N + n]) = v;
            }
        }
    }
}

// ---------------------------------------------------------------------------
// Scores via TF32 MMA + per-column-tile softmax partial stats.
// Writes raw scaled scores to attn and (max, sumexp) partials per 128-col tile.
// ---------------------------------------------------------------------------
__global__ void scores_tc_kernel(float* __restrict__ attn) {
    const int bh = blockIdx.z;
    const int b = bh >> 4;
    const int h = bh & 15;
    const int bm = blockIdx.x * 128;
    const int bn = blockIdx.y * 128;

    __shared__ unsigned Qs[128][36];
    __shared__ unsigned Ks[128][36];
    __shared__ float pm_s[4][128];   // per n-warp partial max
    __shared__ float ps_s[4][128];   // per n-warp partial sumexp

    const int tid = threadIdx.x;
    const int warp = tid >> 5;
    const int lane = tid & 31;
    const int wm = (warp >> 2) * 64;
    const int wn = (warp & 3) * 32;
    const int lr = lane >> 2;
    const int lc = lane & 3;

    float c[4][4][4] = {};

    for (int k0 = 0; k0 < DK; k0 += 32) {
        {
            const int r = tid >> 1;
            const int cb = (tid & 1) * 16;
            const float* src = &g_Q[(size_t)(b * SS + bm + r) * DM + h * DK + k0 + cb];
            #pragma unroll
            for (int i = 0; i < 4; i++) {
                float4 v = *reinterpret_cast<const float4*>(src + i * 4);
                Qs[r][cb + i*4 + 0] = f2tf(v.x);
                Qs[r][cb + i*4 + 1] = f2tf(v.y);
                Qs[r][cb + i*4 + 2] = f2tf(v.z);
                Qs[r][cb + i*4 + 3] = f2tf(v.w);
            }
            const float* ksrc = &g_Kp[(size_t)(b * SS + bn + r) * DK + k0 + cb];
            #pragma unroll
            for (int i = 0; i < 4; i++) {
                float4 v = *reinterpret_cast<const float4*>(ksrc + i * 4);
                Ks[r][cb + i*4 + 0] = f2tf(v.x);
                Ks[r][cb + i*4 + 1] = f2tf(v.y);
                Ks[r][cb + i*4 + 2] = f2tf(v.z);
                Ks[r][cb + i*4 + 3] = f2tf(v.w);
            }
        }
        __syncthreads();

        #pragma unroll
        for (int ks = 0; ks < 4; ks++) {
            const int kb = ks * 8;
            unsigned a[4][4], bf[4][2];
            #pragma unroll
            for (int mt = 0; mt < 4; mt++) {
                int r0 = wm + mt * 16 + lr;
                a[mt][0] = Qs[r0    ][kb + lc];
                a[mt][1] = Qs[r0 + 8][kb + lc];
                a[mt][2] = Qs[r0    ][kb + 4 + lc];
                a[mt][3] = Qs[r0 + 8][kb + 4 + lc];
            }
            #pragma unroll
            for (int nt = 0; nt < 4; nt++) {
                int n0 = wn + nt * 8 + lr;
                bf[nt][0] = Ks[n0][kb + lc];
                bf[nt][1] = Ks[n0][kb + 4 + lc];
            }
            #pragma unroll
            for (int mt = 0; mt < 4; mt++)
                #pragma unroll
                for (int nt = 0; nt < 4; nt++)
                    mma_tf32(c[mt][nt], a[mt], bf[nt]);
        }
        __syncthreads();
    }

    // Epilogue: scale, store raw scores, accumulate per-row partial stats.
    const float scale = 0.125f;
    #pragma unroll
    for (int mt = 0; mt < 4; mt++) {
        #pragma unroll
        for (int half = 0; half < 2; half++) {
            const int rloc = wm + mt * 16 + lr + half * 8;   // local row 0..127
            size_t rowbase = ((size_t)bh * SS + bm + rloc) * SS;

            float vals[8];
            #pragma unroll
            for (int nt = 0; nt < 4; nt++) {
                vals[nt * 2 + 0] = c[mt][nt][half * 2 + 0] * scale;
                vals[nt * 2 + 1] = c[mt][nt][half * 2 + 1] * scale;
                int n = bn + wn + nt * 8 + lc * 2;
                float2 v = {vals[nt * 2 + 0], vals[nt * 2 + 1]};
                *reinterpret_cast<float2*>(&attn[rowbase + n]) = v;
            }

            // thread-local (max, sumexp) over its 8 values in this row
            float tm = vals[0];
            #pragma unroll
            for (int i = 1; i < 8; i++) tm = fmaxf(tm, vals[i]);
            float ts = 0.f;
            #pragma unroll
            for (int i = 0; i < 8; i++) ts += __expf(vals[i] - tm);

            // combine across the 4 lanes (lc) holding this row
            #pragma unroll
            for (int d = 1; d <= 2; d <<= 1) {
                float om = __shfl_xor_sync(0xffffffffu, tm, d);
                float os = __shfl_xor_sync(0xffffffffu, ts, d);
                float M = fmaxf(tm, om);
                ts = ts * __expf(tm - M) + os * __expf(om - M);
                tm = M;
            }
            if (lc == 0) {
                pm_s[warp & 3][rloc] = tm;
                ps_s[warp & 3][rloc] = ts;
            }
        }
    }
    __syncthreads();

    // Combine the 4 n-warp partials per row; write tile stats to global.
    if (tid < 128) {
        float M = pm_s[0][tid];
        #pragma unroll
        for (int w = 1; w < 4; w++) M = fmaxf(M, pm_s[w][tid]);
        float S = 0.f;
        #pragma unroll
        for (int w = 0; w < 4; w++) S += ps_s[w][tid] * __expf(pm_s[w][tid] - M);
        g_pm[bh][blockIdx.y][bm + tid] = M;
        g_ps[bh][blockIdx.y][bm + tid] = S;
    }
}

// ---------------------------------------------------------------------------
// Combine the 16 column-tile partials into per-row (max, 1/sum).
// One thread per (bh, row).
// ---------------------------------------------------------------------------
__global__ void stats_combine_kernel() {
    const int idx = blockIdx.x * blockDim.x + threadIdx.x;   // 0 .. BHX*SS-1
    const int bh = idx >> 11;          // / SS
    const int row = idx & (SS - 1);

    float M = g_pm[bh][0][row];
    #pragma unroll
    for (int t = 1; t < NTILES; t++) M = fmaxf(M, g_pm[bh][t][row]);
    float S = 0.f;
    #pragma unroll
    for (int t = 0; t < NTILES; t++) S += g_ps[bh][t][row] * __expf(g_pm[bh][t][row] - M);

    g_rowM [bh][row] = M;
    g_rowIS[bh][row] = 1.f / S;
}

// ---------------------------------------------------------------------------
// av: reads RAW scores, applies p = exp(x-M)*invS inline (writing p back to
// attn => the softmax output), and computes heads = p @ V via TF32 MMA.
// Stored in the REFERENCE reshape layout.
// ---------------------------------------------------------------------------
__global__ void av_tc_kernel(float* __restrict__ attn) {
    const int bh = blockIdx.y;
    const int b = bh >> 4;
    const int h = bh & 15;
    const int bm = blockIdx.x * 128;

    float* A = attn + (size_t)bh * SS * SS;

    __shared__ unsigned As_[128][36];
    __shared__ unsigned Vs[32][68];

    const int tid = threadIdx.x;
    const int warp = tid >> 5;
    const int lane = tid & 31;
    const int wm = (warp >> 1) * 32;
    const int wn = (warp & 1) * 32;
    const int lr = lane >> 2;
    const int lc = lane & 3;

    // Loading thread's fixed row -> fetch softmax stats once.
    const int ldr = tid >> 1;                  // 0..127
    const float rowM  = g_rowM [bh][bm + ldr];
    const float rowIS = g_rowIS[bh][bm + ldr];

    float c[2][4][4] = {};

    for (int k0 = 0; k0 < SS; k0 += 32) {
        {
            const int cb = (tid & 1) * 16;
            float* src = &A[(size_t)(bm + ldr) * SS + k0 + cb];
            #pragma unroll
            for (int i = 0; i < 4; i++) {
                float4 v = *reinterpret_cast<const float4*>(src + i * 4);
                v.x = __expf(v.x - rowM) * rowIS;
                v.y = __expf(v.y - rowM) * rowIS;
                v.z = __expf(v.z - rowM) * rowIS;
                v.w = __expf(v.w - rowM) * rowIS;
                *reinterpret_cast<float4*>(src + i * 4) = v;   // softmax output
                As_[ldr][cb + i*4 + 0] = f2tf(v.x);
                As_[ldr][cb + i*4 + 1] = f2tf(v.y);
                As_[ldr][cb + i*4 + 2] = f2tf(v.z);
                As_[ldr][cb + i*4 + 3] = f2tf(v.w);
            }
        }
        {
            const int r = tid >> 3;
            const int cb = (tid & 7) * 8;
            const float* src = &g_Vp[(size_t)(b * SS + k0 + r) * DK + cb];
            #pragma unroll
            for (int i = 0; i < 2; i++) {
                float4 v = *reinterpret_cast<const float4*>(src + i * 4);
                Vs[r][cb + i*4 + 0] = f2tf(v.x);
                Vs[r][cb + i*4 + 1] = f2tf(v.y);
                Vs[r][cb + i*4 + 2] = f2tf(v.z);
                Vs[r][cb + i*4 + 3] = f2tf(v.w);
            }
        }
        __syncthreads();

        #pragma unroll
        for (int ks = 0; ks < 4; ks++) {
            const int kb = ks * 8;
            unsigned a[2][4], bf[4][2];
            #pragma unroll
            for (int mt = 0; mt < 2; mt++) {
                int r0 = wm + mt * 16 + lr;
                a[mt][0] = As_[r0    ][kb + lc];
                a[mt][1] = As_[r0 + 8][kb + lc];
                a[mt][2] = As_[r0    ][kb + 4 + lc];
                a[mt][3] = As_[r0 + 8][kb + 4 + lc];
            }
            #pragma unroll
            for (int nt = 0; nt < 4; nt++) {
                int n0 = wn + nt * 8 + lr;
                bf[nt][0] = Vs[kb + lc    ][n0];
                bf[nt][1] = Vs[kb + 4 + lc][n0];
            }
            #pragma unroll
            for (int mt = 0; mt < 2; mt++)
                #pragma unroll
                for (int nt = 0; nt < 4; nt++)
                    mma_tf32(c[mt][nt], a[mt], bf[nt]);
        }
        __syncthreads();
    }

    // Scrambled-reshape store (matches reference heads.reshape(B,S,D_MODEL)).
    #pragma unroll
    for (int mt = 0; mt < 2; mt++) {
        #pragma unroll
        for (int half = 0; half < 2; half++) {
            int sq = bm + wm + mt * 16 + lr + half * 8;
            size_t row = (size_t)b * SS + h * 128 + (sq >> 4);
            int cpart = (sq & 15) * 64;
            #pragma unroll
            for (int nt = 0; nt < 4; nt++) {
                int d = wn + nt * 8 + lc * 2;
                float2 v;
                v.x = c[mt][nt][half * 2 + 0];
                v.y = c[mt][nt][half * 2 + 1];
                *reinterpret_cast<float2*>(&g_AO[row * DM + cpart + d]) = v;
            }
        }
    }
}

// ---------------------------------------------------------------------------
// Launch
// ---------------------------------------------------------------------------
extern "C" void kernel_launch(void* const* d_in, const int* in_sizes, int n_in,
                              void* d_out, int out_size) {
    const float* query = (const float*)d_in[0];
    const float* key_  = (const float*)d_in[1];
    const float* value = (const float*)d_in[2];
    const float* w_q   = (const float*)d_in[3];
    const float* b_q   = (const float*)d_in[4];
    const float* w_k   = (const float*)d_in[5];
    const float* b_k   = (const float*)d_in[6];
    const float* w_v   = (const float*)d_in[7];
    const float* b_v   = (const float*)d_in[8];
    const float* w_o   = (const float*)d_in[9];
    const float* b_o   = (const float*)d_in[10];

    float *Qp, *Kp, *Vp, *AO, *attn_scr;
    cudaGetSymbolAddress((void**)&Qp, g_Q);
    cudaGetSymbolAddress((void**)&Kp, g_Kp);
    cudaGetSymbolAddress((void**)&Vp, g_Vp);
    cudaGetSymbolAddress((void**)&AO, g_AO);
    cudaGetSymbolAddress((void**)&attn_scr, g_attn_scratch);

    float* out = (float*)d_out;
    const size_t OUT_ELEMS  = (size_t)BB * SS * DM;
    const size_t ATTN_ELEMS = (size_t)BB * NH * SS * SS;

    float* attn = ((size_t)out_size >= OUT_ELEMS + ATTN_ELEMS)
                      ? (out + OUT_ELEMS)
                      : attn_scr;

    const int M = BB * SS;   // 4096
    dim3 thr(256);

    // Projections
    gemm_bias_tf32x3_kernel<<<dim3(M / 128, DM / 128), thr>>>(query, w_q, b_q, Qp, M, DM, DM);
    gemm_bias_kernel<<<dim3(M / 64, 1), thr>>>(key_,  w_k, b_k, Kp, M, DM, DK);
    gemm_bias_kernel<<<dim3(M / 64, 1), thr>>>(value, w_v, b_v, Vp, M, DM, DK);

    // Scores (raw, + partial softmax stats)
    scores_tc_kernel<<<dim3(SS / 128, SS / 128, BHX), thr>>>(attn);

    // Combine stats: per-row (max, 1/sum)
    stats_combine_kernel<<<dim3(BHX * SS / 256), thr>>>();

    // av: inline softmax (writes normalized attn) + p @ V
    av_tc_kernel<<<dim3(SS / 128, BHX), thr>>>(attn);

    // Output projection
    gemm_bias_tf32x3_kernel<<<dim3(M / 128, DM / 128), thr>>>(AO, w_o, b_o, out, M, DM, DM);
}

// round 13
// speedup vs baseline: 1.3132x; 1.3132x over previous
#include <cuda_runtime.h>
#include <cuda_bf16.h>
#include <math.h>
#include <stddef.h>

// Problem constants
#define BB 2
#define SS 2048
#define DM 1024
#define NH 16
#define DK 64
#define BHX (BB * NH)   // 32

// ---------------------------------------------------------------------------
// Scratch (device globals; no allocation allowed)
// ---------------------------------------------------------------------------
__device__ float g_Q [(size_t)BB * SS * DM];
__device__ float g_Kp[(size_t)BB * SS * DK];
__device__ float g_Vp[(size_t)BB * SS * DK];
__device__ float g_AO[(size_t)BB * SS * DM];
__device__ float g_attn_scratch[(size_t)BB * NH * SS * SS];

// ---------------------------------------------------------------------------
// TF32 helpers (fragment layouts validated in R7)
// ---------------------------------------------------------------------------
__device__ __forceinline__ unsigned f2tf(float x) {
    unsigned r;
    asm("cvt.rna.tf32.f32 %0, %1;" : "=r"(r) : "f"(x));
    return r;
}

__device__ __forceinline__ void mma_tf32(float c[4], const unsigned a[4], const unsigned b[2]) {
    asm volatile(
        "mma.sync.aligned.m16n8k8.row.col.f32.tf32.tf32.f32 "
        "{%0,%1,%2,%3}, {%4,%5,%6,%7}, {%8,%9}, {%0,%1,%2,%3};"
        : "+f"(c[0]), "+f"(c[1]), "+f"(c[2]), "+f"(c[3])
        : "r"(a[0]), "r"(a[1]), "r"(a[2]), "r"(a[3]), "r"(b[0]), "r"(b[1]));
}

// ---------------------------------------------------------------------------
// BF16 helpers (m16n8k16; layout = two stacked k8 layouts with packed pairs)
// ---------------------------------------------------------------------------
__device__ __forceinline__ void mma_bf16(float c[4], const unsigned a[4], const unsigned b[2]) {
    asm volatile(
        "mma.sync.aligned.m16n8k16.row.col.f32.bf16.bf16.f32 "
        "{%0,%1,%2,%3}, {%4,%5,%6,%7}, {%8,%9}, {%0,%1,%2,%3};"
        : "+f"(c[0]), "+f"(c[1]), "+f"(c[2]), "+f"(c[3])
        : "r"(a[0]), "r"(a[1]), "r"(a[2]), "r"(a[3]), "r"(b[0]), "r"(b[1]));
}

// Split (x,y) into packed bf16 hi pair + packed bf16 lo (residual) pair.
// Element 0 (x) occupies the low 16 bits per bf16x2 convention.
__device__ __forceinline__ void split2_bf16(float x, float y, unsigned& h, unsigned& l) {
    __nv_bfloat16 hx = __float2bfloat16_rn(x);
    __nv_bfloat16 hy = __float2bfloat16_rn(y);
    __nv_bfloat16 lx = __float2bfloat16_rn(x - __bfloat162float(hx));
    __nv_bfloat16 ly = __float2bfloat16_rn(y - __bfloat162float(hy));
    h = (unsigned)__bfloat16_as_ushort(hx) | ((unsigned)__bfloat16_as_ushort(hy) << 16);
    l = (unsigned)__bfloat16_as_ushort(lx) | ((unsigned)__bfloat16_as_ushort(ly) << 16);
}

// ---------------------------------------------------------------------------
// SIMT fp32 GEMM with bias (small K/V projections, N=64)
// ---------------------------------------------------------------------------
__global__ void gemm_bias_kernel(const float* __restrict__ A,
                                 const float* __restrict__ W,
                                 const float* __restrict__ bias,
                                 float* __restrict__ C,
                                 int M, int K, int N) {
    __shared__ float As[16][68];
    __shared__ float Ws[16][64];

    const int tid = threadIdx.x;
    const int tx = tid & 15;
    const int ty = tid >> 4;
    const int bm = blockIdx.x * 64;
    const int bn = blockIdx.y * 64;

    float acc[4][4] = {};

    for (int k0 = 0; k0 < K; k0 += 16) {
        #pragma unroll
        for (int i = tid; i < 64 * 16; i += 256) {
            int m = i >> 4, k = i & 15;
            As[k][m] = A[(size_t)(bm + m) * K + k0 + k];
        }
        #pragma unroll
        for (int i = tid; i < 16 * 64; i += 256) {
            int k = i >> 6, n = i & 63;
            Ws[k][n] = W[(size_t)(k0 + k) * N + bn + n];
        }
        __syncthreads();

        #pragma unroll
        for (int k = 0; k < 16; k++) {
            float4 avv = *reinterpret_cast<const float4*>(&As[k][ty * 4]);
            float a[4] = {avv.x, avv.y, avv.z, avv.w};
            float4 bv = *reinterpret_cast<const float4*>(&Ws[k][tx * 4]);
            float b[4] = {bv.x, bv.y, bv.z, bv.w};
            #pragma unroll
            for (int i = 0; i < 4; i++)
                #pragma unroll
                for (int j = 0; j < 4; j++)
                    acc[i][j] = fmaf(a[i], b[j], acc[i][j]);
        }
        __syncthreads();
    }

    #pragma unroll
    for (int i = 0; i < 4; i++) {
        int m = bm + ty * 4 + i;
        #pragma unroll
        for (int j = 0; j < 4; j++) {
            int n = bn + tx * 4 + j;
            C[(size_t)m * N + n] = acc[i][j] + bias[n];
        }
    }
}

// ---------------------------------------------------------------------------
// BF16-split ("bf16x3") tensor-core GEMM with bias (~17-bit mantissa):
//   C[M,N] = A[M,K] @ W[K,N] + bias[N]
// Block 128m x 128n; 8 warps 2(m) x 4(n); warp 64x32; BK=16 (one k16 step).
// Smem packs bf16 pairs along k: X[row][c] holds k={2c,2c+1}. Stride 13
// (odd) => conflict-free fragment loads.
// ---------------------------------------------------------------------------
__global__ void gemm_bias_bf16x3_kernel(const float* __restrict__ A,
                                        const float* __restrict__ W,
                                        const float* __restrict__ bias,
                                        float* __restrict__ C,
                                        int M, int K, int N) {
    __shared__ unsigned Ah[128][13];   // [m][kpair]
    __shared__ unsigned Al[128][13];
    __shared__ unsigned Wh[128][13];   // [n][kpair]
    __shared__ unsigned Wl[128][13];

    const int tid = threadIdx.x;
    const int warp = tid >> 5;
    const int lane = tid & 31;
    const int wm = (warp >> 2) * 64;   // 0 or 64
    const int wn = (warp & 3) * 32;    // 0,32,64,96
    const int lr = lane >> 2;          // 0..7
    const int lc = lane & 3;           // 0..3
    const int bm = blockIdx.x * 128;
    const int bn = blockIdx.y * 128;

    float c[4][4][4] = {};             // [mtile][ntile][frag]

    for (int k0 = 0; k0 < K; k0 += 16) {
        // A tile 128x16: thread -> row tid>>1, 8 floats at col (tid&1)*8
        {
            const int r = tid >> 1;
            const int cb = (tid & 1) * 8;        // float col base
            const int pb = (tid & 1) * 4;        // packed col base
            const float* src = &A[(size_t)(bm + r) * K + k0 + cb];
            float4 v0 = *reinterpret_cast<const float4*>(src);
            float4 v1 = *reinterpret_cast<const float4*>(src + 4);
            unsigned h, l;
            split2_bf16(v0.x, v0.y, h, l); Ah[r][pb + 0] = h; Al[r][pb + 0] = l;
            split2_bf16(v0.z, v0.w, h, l); Ah[r][pb + 1] = h; Al[r][pb + 1] = l;
            split2_bf16(v1.x, v1.y, h, l); Ah[r][pb + 2] = h; Al[r][pb + 2] = l;
            split2_bf16(v1.z, v1.w, h, l); Ah[r][pb + 3] = h; Al[r][pb + 3] = l;
        }
        // W tile 16x128 -> transpose to [n][kpair].
        // warp w handles k rows {2w, 2w+1}; lane covers n = lane*4 .. +3.
        {
            const int kk2 = warp * 2;
            const int nb = lane * 4;
            const float* src0 = &W[(size_t)(k0 + kk2    ) * N + bn + nb];
            const float* src1 = &W[(size_t)(k0 + kk2 + 1) * N + bn + nb];
            float4 r0 = *reinterpret_cast<const float4*>(src0);
            float4 r1 = *reinterpret_cast<const float4*>(src1);
            unsigned h, l;
            split2_bf16(r0.x, r1.x, h, l); Wh[nb + 0][warp] = h; Wl[nb + 0][warp] = l;
            split2_bf16(r0.y, r1.y, h, l); Wh[nb + 1][warp] = h; Wl[nb + 1][warp] = l;
            split2_bf16(r0.z, r1.z, h, l); Wh[nb + 2][warp] = h; Wl[nb + 2][warp] = l;
            split2_bf16(r0.w, r1.w, h, l); Wh[nb + 3][warp] = h; Wl[nb + 3][warp] = l;
        }
        __syncthreads();

        // One k16 MMA step per tile.
        unsigned ah[4][4], al[4][4], bh[4][2], bl[4][2];
        #pragma unroll
        for (int mt = 0; mt < 4; mt++) {
            int r0 = wm + mt * 16 + lr;
            ah[mt][0] = Ah[r0    ][lc];
            ah[mt][1] = Ah[r0 + 8][lc];
            ah[mt][2] = Ah[r0    ][lc + 4];
            ah[mt][3] = Ah[r0 + 8][lc + 4];
            al[mt][0] = Al[r0    ][lc];
            al[mt][1] = Al[r0 + 8][lc];
            al[mt][2] = Al[r0    ][lc + 4];
            al[mt][3] = Al[r0 + 8][lc + 4];
        }
        #pragma unroll
        for (int nt = 0; nt < 4; nt++) {
            int n0 = wn + nt * 8 + lr;
            bh[nt][0] = Wh[n0][lc];
            bh[nt][1] = Wh[n0][lc + 4];
            bl[nt][0] = Wl[n0][lc];
            bl[nt][1] = Wl[n0][lc + 4];
        }
        #pragma unroll
        for (int mt = 0; mt < 4; mt++)
            #pragma unroll
            for (int nt = 0; nt < 4; nt++) {
                mma_bf16(c[mt][nt], al[mt], bh[nt]);   // small terms first
                mma_bf16(c[mt][nt], ah[mt], bl[nt]);
                mma_bf16(c[mt][nt], ah[mt], bh[nt]);
            }
        __syncthreads();
    }

    // Epilogue: add bias, store float2.
    #pragma unroll
    for (int mt = 0; mt < 4; mt++) {
        #pragma unroll
        for (int half = 0; half < 2; half++) {
            int m = bm + wm + mt * 16 + lr + half * 8;
            #pragma unroll
            for (int nt = 0; nt < 4; nt++) {
                int n = bn + wn + nt * 8 + lc * 2;
                float2 bv = *reinterpret_cast<const float2*>(&bias[n]);
                float2 v;
                v.x = c[mt][nt][half * 2 + 0] + bv.x;
                v.y = c[mt][nt][half * 2 + 1] + bv.y;
                *reinterpret_cast<float2*>(&C[(size_t)m * N + n]) = v;
            }
        }
    }
}

// ---------------------------------------------------------------------------
// Scores via TF32 MMA: attn_pre[bh,i,j] = (Q . K) * 0.125   (R9 version)
// ---------------------------------------------------------------------------
__global__ void scores_tc_kernel(float* __restrict__ attn) {
    const int bh = blockIdx.z;
    const int b = bh >> 4;
    const int h = bh & 15;
    const int bm = blockIdx.x * 128;
    const int bn = blockIdx.y * 128;

    __shared__ unsigned Qs[128][36];
    __shared__ unsigned Ks[128][36];

    const int tid = threadIdx.x;
    const int warp = tid >> 5;
    const int lane = tid & 31;
    const int wm = (warp >> 2) * 64;
    const int wn = (warp & 3) * 32;
    const int lr = lane >> 2;
    const int lc = lane & 3;

    float c[4][4][4] = {};

    for (int k0 = 0; k0 < DK; k0 += 32) {
        {
            const int r = tid >> 1;
            const int cb = (tid & 1) * 16;
            const float* src = &g_Q[(size_t)(b * SS + bm + r) * DM + h * DK + k0 + cb];
            #pragma unroll
            for (int i = 0; i < 4; i++) {
                float4 v = *reinterpret_cast<const float4*>(src + i * 4);
                Qs[r][cb + i*4 + 0] = f2tf(v.x);
                Qs[r][cb + i*4 + 1] = f2tf(v.y);
                Qs[r][cb + i*4 + 2] = f2tf(v.z);
                Qs[r][cb + i*4 + 3] = f2tf(v.w);
            }
            const float* ksrc = &g_Kp[(size_t)(b * SS + bn + r) * DK + k0 + cb];
            #pragma unroll
            for (int i = 0; i < 4; i++) {
                float4 v = *reinterpret_cast<const float4*>(ksrc + i * 4);
                Ks[r][cb + i*4 + 0] = f2tf(v.x);
                Ks[r][cb + i*4 + 1] = f2tf(v.y);
                Ks[r][cb + i*4 + 2] = f2tf(v.z);
                Ks[r][cb + i*4 + 3] = f2tf(v.w);
            }
        }
        __syncthreads();

        #pragma unroll
        for (int ks = 0; ks < 4; ks++) {
            const int kb = ks * 8;
            unsigned a[4][4], bf[4][2];
            #pragma unroll
            for (int mt = 0; mt < 4; mt++) {
                int r0 = wm + mt * 16 + lr;
                a[mt][0] = Qs[r0    ][kb + lc];
                a[mt][1] = Qs[r0 + 8][kb + lc];
                a[mt][2] = Qs[r0    ][kb + 4 + lc];
                a[mt][3] = Qs[r0 + 8][kb + 4 + lc];
            }
            #pragma unroll
            for (int nt = 0; nt < 4; nt++) {
                int n0 = wn + nt * 8 + lr;
                bf[nt][0] = Ks[n0][kb + lc];
                bf[nt][1] = Ks[n0][kb + 4 + lc];
            }
            #pragma unroll
            for (int mt = 0; mt < 4; mt++)
                #pragma unroll
                for (int nt = 0; nt < 4; nt++)
                    mma_tf32(c[mt][nt], a[mt], bf[nt]);
        }
        __syncthreads();
    }

    const float scale = 0.125f;
    #pragma unroll
    for (int mt = 0; mt < 4; mt++) {
        #pragma unroll
        for (int half = 0; half < 2; half++) {
            int m = bm + wm + mt * 16 + lr + half * 8;
            size_t rowbase = ((size_t)bh * SS + m) * SS;
            #pragma unroll
            for (int nt = 0; nt < 4; nt++) {
                int n = bn + wn + nt * 8 + lc * 2;
                float2 v;
                v.x = c[mt][nt][half * 2 + 0] * scale;
                v.y = c[mt][nt][half * 2 + 1] * scale;
                *reinterpret_cast<float2*>(&attn[rowbase + n]) = v;
            }
        }
    }
}

// ---------------------------------------------------------------------------
// Row softmax over the last dim (S=2048). One block per row. In-place.
// ---------------------------------------------------------------------------
__global__ void softmax_kernel(float* __restrict__ attn) {
    const size_t row = blockIdx.x;
    float* p = attn + row * SS;
    const int tid = threadIdx.x;

    __shared__ float red[256];

    float v[8];
    float m = -INFINITY;
    #pragma unroll
    for (int i = 0; i < 8; i++) {
        v[i] = p[tid + i * 256];
        m = fmaxf(m, v[i]);
    }
    red[tid] = m;
    __syncthreads();
    #pragma unroll
    for (int s = 128; s > 0; s >>= 1) {
        if (tid < s) red[tid] = fmaxf(red[tid], red[tid + s]);
        __syncthreads();
    }
    m = red[0];
    __syncthreads();

    float sum = 0.f;
    #pragma unroll
    for (int i = 0; i < 8; i++) {
        v[i] = __expf(v[i] - m);
        sum += v[i];
    }
    red[tid] = sum;
    __syncthreads();
    #pragma unroll
    for (int s = 128; s > 0; s >>= 1) {
        if (tid < s) red[tid] += red[tid + s];
        __syncthreads();
    }
    const float inv = 1.f / red[0];

    #pragma unroll
    for (int i = 0; i < 8; i++)
        p[tid + i * 256] = v[i] * inv;
}

// ---------------------------------------------------------------------------
// heads = attn @ V via TF32 MMA, stored in the REFERENCE reshape layout. (R9)
// ---------------------------------------------------------------------------
__global__ void av_tc_kernel(const float* __restrict__ attn) {
    const int bh = blockIdx.y;
    const int b = bh >> 4;
    const int h = bh & 15;
    const int bm = blockIdx.x * 128;

    const float* A = attn + (size_t)bh * SS * SS;

    __shared__ unsigned As_[128][36];
    __shared__ unsigned Vs[32][68];

    const int tid = threadIdx.x;
    const int warp = tid >> 5;
    const int lane = tid & 31;
    const int wm = (warp >> 1) * 32;
    const int wn = (warp & 1) * 32;
    const int lr = lane >> 2;
    const int lc = lane & 3;

    float c[2][4][4] = {};

    for (int k0 = 0; k0 < SS; k0 += 32) {
        {
            const int r = tid >> 1;
            const int cb = (tid & 1) * 16;
            const float* src = &A[(size_t)(bm + r) * SS + k0 + cb];
            #pragma unroll
            for (int i = 0; i < 4; i++) {
                float4 v = *reinterpret_cast<const float4*>(src + i * 4);
                As_[r][cb + i*4 + 0] = f2tf(v.x);
                As_[r][cb + i*4 + 1] = f2tf(v.y);
                As_[r][cb + i*4 + 2] = f2tf(v.z);
                As_[r][cb + i*4 + 3] = f2tf(v.w);
            }
        }
        {
            const int r = tid >> 3;
            const int cb = (tid & 7) * 8;
            const float* src = &g_Vp[(size_t)(b * SS + k0 + r) * DK + cb];
            #pragma unroll
            for (int i = 0; i < 2; i++) {
                float4 v = *reinterpret_cast<const float4*>(src + i * 4);
                Vs[r][cb + i*4 + 0] = f2tf(v.x);
                Vs[r][cb + i*4 + 1] = f2tf(v.y);
                Vs[r][cb + i*4 + 2] = f2tf(v.z);
                Vs[r][cb + i*4 + 3] = f2tf(v.w);
            }
        }
        __syncthreads();

        #pragma unroll
        for (int ks = 0; ks < 4; ks++) {
            const int kb = ks * 8;
            unsigned a[2][4], bf[4][2];
            #pragma unroll
            for (int mt = 0; mt < 2; mt++) {
                int r0 = wm + mt * 16 + lr;
                a[mt][0] = As_[r0    ][kb + lc];
                a[mt][1] = As_[r0 + 8][kb + lc];
                a[mt][2] = As_[r0    ][kb + 4 + lc];
                a[mt][3] = As_[r0 + 8][kb + 4 + lc];
            }
            #pragma unroll
            for (int nt = 0; nt < 4; nt++) {
                int n0 = wn + nt * 8 + lr;
                bf[nt][0] = Vs[kb + lc    ][n0];
                bf[nt][1] = Vs[kb + 4 + lc][n0];
            }
            #pragma unroll
            for (int mt = 0; mt < 2; mt++)
                #pragma unroll
                for (int nt = 0; nt < 4; nt++)
                    mma_tf32(c[mt][nt], a[mt], bf[nt]);
        }
        __syncthreads();
    }

    // Scrambled-reshape store (matches reference heads.reshape(B,S,D_MODEL)).
    #pragma unroll
    for (int mt = 0; mt < 2; mt++) {
        #pragma unroll
        for (int half = 0; half < 2; half++) {
            int sq = bm + wm + mt * 16 + lr + half * 8;
            size_t row = (size_t)b * SS + h * 128 + (sq >> 4);
            int cpart = (sq & 15) * 64;
            #pragma unroll
            for (int nt = 0; nt < 4; nt++) {
                int d = wn + nt * 8 + lc * 2;
                float2 v;
                v.x = c[mt][nt][half * 2 + 0];
                v.y = c[mt][nt][half * 2 + 1];
                *reinterpret_cast<float2*>(&g_AO[row * DM + cpart + d]) = v;
            }
        }
    }
}

// ---------------------------------------------------------------------------
// Launch
// ---------------------------------------------------------------------------
extern "C" void kernel_launch(void* const* d_in, const int* in_sizes, int n_in,
                              void* d_out, int out_size) {
    const float* query = (const float*)d_in[0];
    const float* key_  = (const float*)d_in[1];
    const float* value = (const float*)d_in[2];
    const float* w_q   = (const float*)d_in[3];
    const float* b_q   = (const float*)d_in[4];
    const float* w_k   = (const float*)d_in[5];
    const float* b_k   = (const float*)d_in[6];
    const float* w_v   = (const float*)d_in[7];
    const float* b_v   = (const float*)d_in[8];
    const float* w_o   = (const float*)d_in[9];
    const float* b_o   = (const float*)d_in[10];

    float *Qp, *Kp, *Vp, *AO, *attn_scr;
    cudaGetSymbolAddress((void**)&Qp, g_Q);
    cudaGetSymbolAddress((void**)&Kp, g_Kp);
    cudaGetSymbolAddress((void**)&Vp, g_Vp);
    cudaGetSymbolAddress((void**)&AO, g_AO);
    cudaGetSymbolAddress((void**)&attn_scr, g_attn_scratch);

    float* out = (float*)d_out;
    const size_t OUT_ELEMS  = (size_t)BB * SS * DM;
    const size_t ATTN_ELEMS = (size_t)BB * NH * SS * SS;

    float* attn = ((size_t)out_size >= OUT_ELEMS + ATTN_ELEMS)
                      ? (out + OUT_ELEMS)
                      : attn_scr;

    const int M = BB * SS;   // 4096
    dim3 thr(256);

    // Big projections: bf16-split tensor cores (~17-bit mantissa)
    gemm_bias_bf16x3_kernel<<<dim3(M / 128, DM / 128), thr>>>(query, w_q, b_q, Qp, M, DM, DM);
    // Small K/V projections: SIMT fp32
    gemm_bias_kernel<<<dim3(M / 64, 1), thr>>>(key_,  w_k, b_k, Kp, M, DM, DK);
    gemm_bias_kernel<<<dim3(M / 64, 1), thr>>>(value, w_v, b_v, Vp, M, DM, DK);

    // Scores (tf32 tensor core) + softmax
    scores_tc_kernel<<<dim3(SS / 128, SS / 128, BHX), thr>>>(attn);
    softmax_kernel<<<dim3((unsigned)((size_t)BHX * SS)), thr>>>(attn);

    // attn @ V (tf32 tensor core, reference reshape layout)
    av_tc_kernel<<<dim3(SS / 128, BHX), thr>>>(attn);

    // Output projection: bf16-split tensor cores
    gemm_bias_bf16x3_kernel<<<dim3(M / 128, DM / 128), thr>>>(AO, w_o, b_o, out, M, DM, DM);
}